// round 6
// baseline (speedup 1.0000x reference)
#include <cuda_runtime.h>
#include <cuda_fp16.h>
#include <cstdint>
#include <cstddef>

// Problem constants
#define BATCH   8
#define SEQ     4096
#define DMODEL  1024
#define NHEAD   16
#define DHEAD   64
#define TOKENS  (BATCH * SEQ)            // 32768
#define GK      DMODEL                   // GEMM K = 1024
#define NQKV    (3 * DMODEL)             // 3072

// ---------------------------------------------------------------------------
// Static scratch (no cudaMalloc allowed)
// ---------------------------------------------------------------------------
__device__ __half g_qkv[(size_t)TOKENS * NQKV];   // packed q|k|v per token (fp16)
__device__ __half g_xh [(size_t)TOKENS * DMODEL];
__device__ __half g_ch [(size_t)TOKENS * DMODEL];

__device__ __half g_whi[4][(size_t)DMODEL * DMODEL];  // wq|wk|wv|wo hi
__device__ __half g_wlo[4][(size_t)DMODEL * DMODEL];  // wq|wk|wv|wo lo
__device__ float  g_bqkv[NQKV];                        // bq|bk|bv packed

// ---------------------------------------------------------------------------
__device__ __forceinline__ uint32_t smem_u32(const void* p) {
    uint32_t a;
    asm("{ .reg .u64 t; cvta.to.shared.u64 t, %1; cvt.u32.u64 %0, t; }"
        : "=r"(a) : "l"(p));
    return a;
}

__device__ __forceinline__ void ldsm_x4(uint32_t (&r)[4], uint32_t addr) {
    asm volatile("ldmatrix.sync.aligned.m8n8.x4.shared.b16 {%0,%1,%2,%3}, [%4];"
                 : "=r"(r[0]), "=r"(r[1]), "=r"(r[2]), "=r"(r[3]) : "r"(addr));
}

__device__ __forceinline__ void mma_f16(float (&d)[4], const uint32_t (&a)[4],
                                        const uint32_t* b) {
    asm volatile(
        "mma.sync.aligned.m16n8k16.row.col.f32.f16.f16.f32 "
        "{%0,%1,%2,%3}, {%4,%5,%6,%7}, {%8,%9}, {%0,%1,%2,%3};"
        : "+f"(d[0]), "+f"(d[1]), "+f"(d[2]), "+f"(d[3])
        : "r"(a[0]), "r"(a[1]), "r"(a[2]), "r"(a[3]), "r"(b[0]), "r"(b[1]));
}

__device__ __forceinline__ void cp16(uint32_t dst, const void* src) {
    asm volatile("cp.async.cg.shared.global [%0], [%1], 16;"
                 :: "r"(dst), "l"(src));
}

// ---------------------------------------------------------------------------
// Prep kernels
// ---------------------------------------------------------------------------
__global__ void conv_f16(const float* __restrict__ src,
                         __half* __restrict__ dst, int n4) {
    int i = blockIdx.x * blockDim.x + threadIdx.x;
    if (i >= n4) return;
    float4 v = reinterpret_cast<const float4*>(src)[i];
    __half h[4] = { __float2half_rn(v.x), __float2half_rn(v.y),
                    __float2half_rn(v.z), __float2half_rn(v.w) };
    reinterpret_cast<uint2*>(dst)[i] = *reinterpret_cast<uint2*>(h);
}

__global__ void split_f16(const float* __restrict__ src,
                          __half* __restrict__ hi,
                          __half* __restrict__ lo, int n4) {
    int i = blockIdx.x * blockDim.x + threadIdx.x;
    if (i >= n4) return;
    float4 v = reinterpret_cast<const float4*>(src)[i];
    float vv[4] = {v.x, v.y, v.z, v.w};
    __half h[4], l[4];
#pragma unroll
    for (int j = 0; j < 4; j++) {
        h[j] = __float2half_rn(vv[j]);
        l[j] = __float2half_rn(vv[j] - __half2float(h[j]));
    }
    reinterpret_cast<uint2*>(hi)[i] = *reinterpret_cast<uint2*>(h);
    reinterpret_cast<uint2*>(lo)[i] = *reinterpret_cast<uint2*>(l);
}

__global__ void pack_bias(const float* __restrict__ bq, const float* __restrict__ bk,
                          const float* __restrict__ bv, float* __restrict__ dst) {
    int i = blockIdx.x * blockDim.x + threadIdx.x;
    if (i < DMODEL) {
        dst[i]              = bq[i];
        dst[i + DMODEL]     = bk[i];
        dst[i + 2 * DMODEL] = bv[i];
    }
}

// ---------------------------------------------------------------------------
// HMMA GEMM: C[M, N] = Ah @ (Whi + Wlo)^T + bias  (fp16x2, 2 products)
// CTA tile 128x128, K-chunk 64, 3-stage cp.async pipeline.
// 8 warps (4 in M x 2 in N), warp tile 32x64. mma.sync m16n8k16 f16.
// OutT = __half (qkv) or float (final projection). ldc = output row stride.
// ---------------------------------------------------------------------------
#define CHUNK       64
#define NCHUNK      (GK / CHUNK)        // 16
#define TILE_BYTES  16384               // 128 x 128B
#define STAGE_BYTES (3 * TILE_BYTES)    // Ah, Whi, Wlo = 49152
#define NSTAGE      3
#define SMEM_DYN    (NSTAGE * STAGE_BYTES)  // 147456

template <typename OutT>
__global__ __launch_bounds__(256, 1) void gemm_f16x2(
    const __half* __restrict__ Ah,
    const __half* __restrict__ Whi, const __half* __restrict__ Wlo,
    const float* __restrict__ bias, OutT* __restrict__ C, int ldc)
{
    extern __shared__ __align__(1024) char smem[];
    const uint32_t sb = smem_u32(smem);
    const int tid  = threadIdx.x;
    const int wid  = tid >> 5;
    const int lane = tid & 31;
    const int wm   = wid & 3;          // warp row (M)
    const int wn   = wid >> 2;         // warp col (N)

    const size_t rowM0 = (size_t)blockIdx.y * 128;
    const int    colN0 = blockIdx.x * 128;

    const char* srcs[3] = {
        (const char*)(Ah  + rowM0 * GK),
        (const char*)(Whi + (size_t)colN0 * GK),
        (const char*)(Wlo + (size_t)colN0 * GK)
    };

    const int a_row = wm * 32 + (lane & 15);                      // + mi*16
    const int a_ku  = lane >> 4;
    const int b_row = wn * 64 + (lane & 7) + ((lane >> 4) << 3);  // + g*16
    const int b_ku  = (lane >> 3) & 1;

    float acc[2][8][4];
#pragma unroll
    for (int mi = 0; mi < 2; mi++)
#pragma unroll
        for (int nf = 0; nf < 8; nf++)
#pragma unroll
            for (int j = 0; j < 4; j++) acc[mi][nf][j] = 0.f;

    auto load_chunk = [&](int c) {
        const uint32_t stage = sb + (c % NSTAGE) * STAGE_BYTES;
        const int k0b = c * CHUNK * 2;
#pragma unroll
        for (int u2 = 0; u2 < 12; u2++) {
            const int g   = tid + u2 * 256;  // 0..3071
            const int t   = g >> 10;
            const int w   = g & 1023;
            const int row = w >> 3;
            const int u   = w & 7;
            const uint32_t dst = stage + t * TILE_BYTES + row * 128
                               + ((u ^ (row & 7)) << 4);
            cp16(dst, srcs[t] + (size_t)row * 2048 + k0b + u * 16);
        }
        asm volatile("cp.async.commit_group;" ::: "memory");
    };

    load_chunk(0);
    load_chunk(1);

    for (int c = 0; c < NCHUNK; c++) {
        if (c + 2 < NCHUNK) {
            load_chunk(c + 2);
            asm volatile("cp.async.wait_group 2;" ::: "memory");
        } else if (c + 1 < NCHUNK) {
            asm volatile("cp.async.wait_group 1;" ::: "memory");
        } else {
            asm volatile("cp.async.wait_group 0;" ::: "memory");
        }
        __syncthreads();

        const uint32_t stage = sb + (c % NSTAGE) * STAGE_BYTES;
        const uint32_t t_ah  = stage;
        const uint32_t t_whi = stage + TILE_BYTES;
        const uint32_t t_wlo = stage + 2 * TILE_BYTES;

#pragma unroll
        for (int ks = 0; ks < 4; ks++) {
            uint32_t ah[2][4];
#pragma unroll
            for (int mi = 0; mi < 2; mi++) {
                const int row = a_row + mi * 16;
                const int u   = ks * 2 + a_ku;
                const uint32_t off = row * 128 + ((u ^ (row & 7)) << 4);
                ldsm_x4(ah[mi], t_ah + off);
            }
            uint32_t bhi[4][4], blo[4][4];
#pragma unroll
            for (int gg = 0; gg < 4; gg++) {
                const int row = b_row + gg * 16;
                const int u   = ks * 2 + b_ku;
                const uint32_t off = row * 128 + ((u ^ (row & 7)) << 4);
                ldsm_x4(bhi[gg], t_whi + off);
                ldsm_x4(blo[gg], t_wlo + off);
            }
#pragma unroll
            for (int mi = 0; mi < 2; mi++)
#pragma unroll
                for (int gg = 0; gg < 4; gg++)
#pragma unroll
                    for (int sub = 0; sub < 2; sub++) {
                        const int nf = gg * 2 + sub;
                        mma_f16(acc[mi][nf], ah[mi], &bhi[gg][sub * 2]);
                        mma_f16(acc[mi][nf], ah[mi], &blo[gg][sub * 2]);
                    }
        }
        __syncthreads();
    }

    // Epilogue
#pragma unroll
    for (int mi = 0; mi < 2; mi++) {
#pragma unroll
        for (int nf = 0; nf < 8; nf++) {
            const int col = colN0 + wn * 64 + nf * 8 + (lane & 3) * 2;
            const float2 bv2 = *reinterpret_cast<const float2*>(bias + col);
#pragma unroll
            for (int rh = 0; rh < 2; rh++) {
                const size_t row = rowM0 + wm * 32 + mi * 16 + (lane >> 2) + rh * 8;
                const float ox = acc[mi][nf][rh * 2 + 0] + bv2.x;
                const float oy = acc[mi][nf][rh * 2 + 1] + bv2.y;
                if constexpr (sizeof(OutT) == 2) {
                    *reinterpret_cast<__half2*>((__half*)C + row * ldc + col) =
                        __floats2half2_rn(ox, oy);
                } else {
                    float2 o; o.x = ox; o.y = oy;
                    *reinterpret_cast<float2*>((float*)C + row * ldc + col) = o;
                }
            }
        }
    }
}

// ---------------------------------------------------------------------------
// Per-token attention on packed fp16 qkv rows; writes ctx fp16.
// One contiguous 6 KB row per token.
// ---------------------------------------------------------------------------
__global__ __launch_bounds__(256) void attn_kernel(
    const __half* __restrict__ QKV, __half* __restrict__ CH)
{
    const size_t base = (size_t)blockIdx.x * NQKV;
    __shared__ __half sqkv[NQKV];       // q[1024] | k[1024] | v[1024]
    __shared__ float  sp[NHEAD][NHEAD];

    const int tid = threadIdx.x;
    // 3072 halves = 384 uint4
#pragma unroll
    for (int i = tid; i < NQKV / 8; i += 256)
        reinterpret_cast<uint4*>(sqkv)[i] =
            reinterpret_cast<const uint4*>(QKV + base)[i];
    __syncthreads();

    const __half* sq = sqkv;
    const __half* sk = sqkv + DMODEL;
    const __half* sv = sqkv + 2 * DMODEL;

    const int h = tid >> 4;
    const int g = tid & 15;
    const int rot = tid & 31;
    float s = 0.f;
#pragma unroll
    for (int dd = 0; dd < DHEAD; dd++) {
        const int d = (dd + rot) & (DHEAD - 1);
        s = fmaf(__half2float(sq[h * DHEAD + d]),
                 __half2float(sk[g * DHEAD + d]), s);
    }
    s *= 0.125f;

    float m = s;
#pragma unroll
    for (int o = 8; o > 0; o >>= 1) m = fmaxf(m, __shfl_xor_sync(0xFFFFFFFFu, m, o, 16));
    const float e = __expf(s - m);
    float sum = e;
#pragma unroll
    for (int o = 8; o > 0; o >>= 1) sum += __shfl_xor_sync(0xFFFFFFFFu, sum, o, 16);
    sp[h][g] = e / sum;
    __syncthreads();

    const size_t obase = (size_t)blockIdx.x * DMODEL;
#pragma unroll
    for (int r = 0; r < 4; r++) {
        const int idx = tid + r * 256;
        const int hh  = idx >> 6;
        const int d   = idx & (DHEAD - 1);
        float a = 0.f;
#pragma unroll
        for (int gg = 0; gg < NHEAD; gg++)
            a = fmaf(sp[hh][gg], __half2float(sv[gg * DHEAD + d]), a);
        CH[obase + idx] = __float2half_rn(a);
    }
}

// ---------------------------------------------------------------------------
extern "C" void kernel_launch(void* const* d_in, const int* in_sizes, int n_in,
                              void* d_out, int out_size)
{
    const float* x  = (const float*)d_in[0];
    const float* wq = (const float*)d_in[1];
    const float* bq = (const float*)d_in[2];
    const float* wk = (const float*)d_in[3];
    const float* bk = (const float*)d_in[4];
    const float* wv = (const float*)d_in[5];
    const float* bv = (const float*)d_in[6];
    const float* wo = (const float*)d_in[7];
    const float* bo = (const float*)d_in[8];
    float* out = (float*)d_out;

    __half *qkv, *xh, *ch, *whi, *wlo;
    float  *bqkv;
    cudaGetSymbolAddress((void**)&qkv,  g_qkv);
    cudaGetSymbolAddress((void**)&xh,   g_xh);
    cudaGetSymbolAddress((void**)&ch,   g_ch);
    cudaGetSymbolAddress((void**)&whi,  g_whi);
    cudaGetSymbolAddress((void**)&wlo,  g_wlo);
    cudaGetSymbolAddress((void**)&bqkv, g_bqkv);

    cudaFuncSetAttribute(gemm_f16x2<__half>,
                         cudaFuncAttributeMaxDynamicSharedMemorySize, SMEM_DYN);
    cudaFuncSetAttribute(gemm_f16x2<float>,
                         cudaFuncAttributeMaxDynamicSharedMemorySize, SMEM_DYN);

    const size_t WN = (size_t)DMODEL * DMODEL;
    const int nx4 = (TOKENS * DMODEL) / 4;
    const int nw4 = (int)(WN / 4);

    conv_f16<<<(nx4 + 255) / 256, 256>>>(x, xh, nx4);
    split_f16<<<(nw4 + 255) / 256, 256>>>(wq, whi + 0 * WN, wlo + 0 * WN, nw4);
    split_f16<<<(nw4 + 255) / 256, 256>>>(wk, whi + 1 * WN, wlo + 1 * WN, nw4);
    split_f16<<<(nw4 + 255) / 256, 256>>>(wv, whi + 2 * WN, wlo + 2 * WN, nw4);
    split_f16<<<(nw4 + 255) / 256, 256>>>(wo, whi + 3 * WN, wlo + 3 * WN, nw4);
    pack_bias<<<(DMODEL + 255) / 256, 256>>>(bq, bk, bv, bqkv);

    // Merged Q|K|V projection: C[32768, 3072] fp16
    dim3 qkvgrid(NQKV / 128, TOKENS / 128);   // (24, 256)
    gemm_f16x2<__half><<<qkvgrid, 256, SMEM_DYN>>>(xh, whi, wlo, bqkv, qkv, NQKV);

    attn_kernel<<<TOKENS, 256>>>(qkv, ch);

    // Output projection: C[32768, 1024] fp32
    dim3 ogrid(DMODEL / 128, TOKENS / 128);   // (8, 256)
    gemm_f16x2<float><<<ogrid, 256, SMEM_DYN>>>(ch, whi + 3 * WN, wlo + 3 * WN,
                                                bo, out, DMODEL);
}

// round 7
// speedup vs baseline: 2.2834x; 2.2834x over previous
#include <cuda_runtime.h>
#include <cuda_fp16.h>
#include <cstdint>
#include <cstddef>

// Problem constants
#define BATCH   8
#define SEQ     4096
#define DMODEL  1024
#define NHEAD   16
#define DHEAD   64
#define TOKENS  (BATCH * SEQ)            // 32768
#define GK      DMODEL                   // GEMM K = 1024

// ---------------------------------------------------------------------------
// Static scratch (no cudaMalloc allowed)
// ---------------------------------------------------------------------------
__device__ float g_q  [(size_t)TOKENS * DMODEL];
__device__ float g_k  [(size_t)TOKENS * DMODEL];
__device__ float g_v  [(size_t)TOKENS * DMODEL];

__device__ __half g_xh [(size_t)TOKENS * DMODEL];
__device__ __half g_ch [(size_t)TOKENS * DMODEL];
__device__ __half g_wh [4][(size_t)DMODEL * DMODEL];   // wq|wk|wv|wo fp16

// ---------------------------------------------------------------------------
__device__ __forceinline__ uint32_t smem_u32(const void* p) {
    uint32_t a;
    asm("{ .reg .u64 t; cvta.to.shared.u64 t, %1; cvt.u32.u64 %0, t; }"
        : "=r"(a) : "l"(p));
    return a;
}

__device__ __forceinline__ void ldsm_x4(uint32_t (&r)[4], uint32_t addr) {
    asm volatile("ldmatrix.sync.aligned.m8n8.x4.shared.b16 {%0,%1,%2,%3}, [%4];"
                 : "=r"(r[0]), "=r"(r[1]), "=r"(r[2]), "=r"(r[3]) : "r"(addr));
}

__device__ __forceinline__ void mma_f16(float (&d)[4], const uint32_t (&a)[4],
                                        const uint32_t* b) {
    asm volatile(
        "mma.sync.aligned.m16n8k16.row.col.f32.f16.f16.f32 "
        "{%0,%1,%2,%3}, {%4,%5,%6,%7}, {%8,%9}, {%0,%1,%2,%3};"
        : "+f"(d[0]), "+f"(d[1]), "+f"(d[2]), "+f"(d[3])
        : "r"(a[0]), "r"(a[1]), "r"(a[2]), "r"(a[3]), "r"(b[0]), "r"(b[1]));
}

__device__ __forceinline__ void cp16(uint32_t dst, const void* src) {
    asm volatile("cp.async.cg.shared.global [%0], [%1], 16;"
                 :: "r"(dst), "l"(src));
}

// ---------------------------------------------------------------------------
// fp32 -> fp16 convert (round-to-nearest), vectorized
// ---------------------------------------------------------------------------
__global__ void conv_f16(const float* __restrict__ src,
                         __half* __restrict__ dst, int n4) {
    int i = blockIdx.x * blockDim.x + threadIdx.x;
    if (i >= n4) return;
    float4 v = reinterpret_cast<const float4*>(src)[i];
    __half h[4] = { __float2half_rn(v.x), __float2half_rn(v.y),
                    __float2half_rn(v.z), __float2half_rn(v.w) };
    reinterpret_cast<uint2*>(dst)[i] = *reinterpret_cast<uint2*>(h);
}

// ---------------------------------------------------------------------------
// HMMA GEMM: C[M,1024] = Ah @ Wh^T + bias   (fp16 single product)
// CTA tile 128x128, K-chunk 64, 4-stage cp.async pipeline.
// 8 warps (4 in M x 2 in N), warp tile 32x64. mma.sync m16n8k16 f16.
// SMEM tiles: 128 rows x 128B, SW128 xor swizzle (conflict-free ldmatrix).
// ---------------------------------------------------------------------------
#define CHUNK       64
#define NCHUNK      (GK / CHUNK)        // 16
#define TILE_BYTES  16384               // 128 x 128B
#define STAGE_BYTES (2 * TILE_BYTES)    // Ah, Wh = 32768
#define NSTAGE      4
#define SMEM_DYN    (NSTAGE * STAGE_BYTES)  // 131072

__global__ __launch_bounds__(256, 1) void gemm_f16(
    const __half* __restrict__ Ah, const __half* __restrict__ Wh,
    const float* __restrict__ bias, float* __restrict__ C)
{
    extern __shared__ __align__(1024) char smem[];
    const uint32_t sb = smem_u32(smem);
    const int tid  = threadIdx.x;
    const int wid  = tid >> 5;
    const int lane = tid & 31;
    const int wm   = wid & 3;          // warp row (M)
    const int wn   = wid >> 2;         // warp col (N)

    const size_t rowM0 = (size_t)blockIdx.y * 128;
    const int    colN0 = blockIdx.x * 128;

    const char* srcA = (const char*)(Ah + rowM0 * GK);
    const char* srcW = (const char*)(Wh + (size_t)colN0 * GK);

    const int a_row = wm * 32 + (lane & 15);                      // + mi*16
    const int a_ku  = lane >> 4;
    const int b_row = wn * 64 + (lane & 7) + ((lane >> 4) << 3);  // + g*16
    const int b_ku  = (lane >> 3) & 1;

    float acc[2][8][4];
#pragma unroll
    for (int mi = 0; mi < 2; mi++)
#pragma unroll
        for (int nf = 0; nf < 8; nf++)
#pragma unroll
            for (int j = 0; j < 4; j++) acc[mi][nf][j] = 0.f;

    // async loader: 8 x 16B per thread per chunk (2 tiles x 1024 units)
    auto load_chunk = [&](int c) {
        const uint32_t stage = sb + (c % NSTAGE) * STAGE_BYTES;
        const int k0b = c * CHUNK * 2;       // byte offset along K
#pragma unroll
        for (int u2 = 0; u2 < 8; u2++) {
            const int g   = tid + u2 * 256;  // 0..2047
            const int t   = g >> 10;         // 0 = A, 1 = W
            const int w   = g & 1023;
            const int row = w >> 3;
            const int u   = w & 7;
            const uint32_t dst = stage + t * TILE_BYTES + row * 128
                               + ((u ^ (row & 7)) << 4);
            const char* src = (t == 0) ? srcA : srcW;
            cp16(dst, src + (size_t)row * 2048 + k0b + u * 16);
        }
        asm volatile("cp.async.commit_group;" ::: "memory");
    };

    load_chunk(0);
    load_chunk(1);
    load_chunk(2);

    for (int c = 0; c < NCHUNK; c++) {
        if (c + 3 < NCHUNK) {
            load_chunk(c + 3);
            asm volatile("cp.async.wait_group 3;" ::: "memory");
        } else if (c + 2 < NCHUNK) {
            asm volatile("cp.async.wait_group 2;" ::: "memory");
        } else if (c + 1 < NCHUNK) {
            asm volatile("cp.async.wait_group 1;" ::: "memory");
        } else {
            asm volatile("cp.async.wait_group 0;" ::: "memory");
        }
        __syncthreads();

        const uint32_t stage = sb + (c % NSTAGE) * STAGE_BYTES;
        const uint32_t t_ah = stage;
        const uint32_t t_wh = stage + TILE_BYTES;

#pragma unroll
        for (int ks = 0; ks < 4; ks++) {
            uint32_t ah[2][4];
#pragma unroll
            for (int mi = 0; mi < 2; mi++) {
                const int row = a_row + mi * 16;
                const int u   = ks * 2 + a_ku;
                const uint32_t off = row * 128 + ((u ^ (row & 7)) << 4);
                ldsm_x4(ah[mi], t_ah + off);
            }
            uint32_t bh[4][4];
#pragma unroll
            for (int gg = 0; gg < 4; gg++) {
                const int row = b_row + gg * 16;
                const int u   = ks * 2 + b_ku;
                const uint32_t off = row * 128 + ((u ^ (row & 7)) << 4);
                ldsm_x4(bh[gg], t_wh + off);
            }
#pragma unroll
            for (int mi = 0; mi < 2; mi++)
#pragma unroll
                for (int gg = 0; gg < 4; gg++)
#pragma unroll
                    for (int sub = 0; sub < 2; sub++)
                        mma_f16(acc[mi][gg * 2 + sub], ah[mi], &bh[gg][sub * 2]);
        }
        __syncthreads();
    }

    // Epilogue: add bias, write float2 per (mi, nf, rowhalf)
#pragma unroll
    for (int mi = 0; mi < 2; mi++) {
#pragma unroll
        for (int nf = 0; nf < 8; nf++) {
            const int col = colN0 + wn * 64 + nf * 8 + (lane & 3) * 2;
            const float2 bv2 = *reinterpret_cast<const float2*>(bias + col);
#pragma unroll
            for (int rh = 0; rh < 2; rh++) {
                const size_t row = rowM0 + wm * 32 + mi * 16 + (lane >> 2) + rh * 8;
                float2 o;
                o.x = acc[mi][nf][rh * 2 + 0] + bv2.x;
                o.y = acc[mi][nf][rh * 2 + 1] + bv2.y;
                *reinterpret_cast<float2*>(C + row * DMODEL + col) = o;
            }
        }
    }
}

// ---------------------------------------------------------------------------
// Per-token attention (identical to the 1579us R5 version):
// fp32 q/k/v in, fp16 ctx out.
// ---------------------------------------------------------------------------
__global__ __launch_bounds__(256) void attn_kernel(
    const float* __restrict__ Q, const float* __restrict__ K,
    const float* __restrict__ V, __half* __restrict__ CH)
{
    const size_t base = (size_t)blockIdx.x * DMODEL;
    __shared__ float sq[DMODEL];
    __shared__ float sk[DMODEL];
    __shared__ float sv[DMODEL];
    __shared__ float sp[NHEAD][NHEAD];

    const int tid = threadIdx.x;
#pragma unroll
    for (int i = tid; i < DMODEL; i += 256) {
        sq[i] = Q[base + i];
        sk[i] = K[base + i];
        sv[i] = V[base + i];
    }
    __syncthreads();

    const int h = tid >> 4;
    const int g = tid & 15;
    const int rot = tid & 31;
    float s = 0.f;
#pragma unroll
    for (int dd = 0; dd < DHEAD; dd++) {
        const int d = (dd + rot) & (DHEAD - 1);
        s = fmaf(sq[h * DHEAD + d], sk[g * DHEAD + d], s);
    }
    s *= 0.125f;

    float m = s;
#pragma unroll
    for (int o = 8; o > 0; o >>= 1) m = fmaxf(m, __shfl_xor_sync(0xFFFFFFFFu, m, o, 16));
    const float e = __expf(s - m);
    float sum = e;
#pragma unroll
    for (int o = 8; o > 0; o >>= 1) sum += __shfl_xor_sync(0xFFFFFFFFu, sum, o, 16);
    sp[h][g] = e / sum;
    __syncthreads();

#pragma unroll
    for (int r = 0; r < 4; r++) {
        const int idx = tid + r * 256;
        const int hh  = idx >> 6;
        const int d   = idx & (DHEAD - 1);
        float a = 0.f;
#pragma unroll
        for (int gg = 0; gg < NHEAD; gg++)
            a = fmaf(sp[hh][gg], sv[gg * DHEAD + d], a);
        CH[base + idx] = __float2half_rn(a);
    }
}

// ---------------------------------------------------------------------------
extern "C" void kernel_launch(void* const* d_in, const int* in_sizes, int n_in,
                              void* d_out, int out_size)
{
    const float* x  = (const float*)d_in[0];
    const float* wq = (const float*)d_in[1];
    const float* bq = (const float*)d_in[2];
    const float* wk = (const float*)d_in[3];
    const float* bk = (const float*)d_in[4];
    const float* wv = (const float*)d_in[5];
    const float* bv = (const float*)d_in[6];
    const float* wo = (const float*)d_in[7];
    const float* bo = (const float*)d_in[8];
    float* out = (float*)d_out;

    float *q, *k, *v;
    cudaGetSymbolAddress((void**)&q, g_q);
    cudaGetSymbolAddress((void**)&k, g_k);
    cudaGetSymbolAddress((void**)&v, g_v);

    __half *xh, *ch, *wh;
    cudaGetSymbolAddress((void**)&xh, g_xh);
    cudaGetSymbolAddress((void**)&ch, g_ch);
    cudaGetSymbolAddress((void**)&wh, g_wh);

    cudaFuncSetAttribute(gemm_f16,
                         cudaFuncAttributeMaxDynamicSharedMemorySize, SMEM_DYN);

    const size_t WN = (size_t)DMODEL * DMODEL;
    const int nx4 = (TOKENS * DMODEL) / 4;
    const int nw4 = (int)(WN / 4);

    conv_f16<<<(nx4 + 255) / 256, 256>>>(x, xh, nx4);
    conv_f16<<<(nw4 + 255) / 256, 256>>>(wq, wh + 0 * WN, nw4);
    conv_f16<<<(nw4 + 255) / 256, 256>>>(wk, wh + 1 * WN, nw4);
    conv_f16<<<(nw4 + 255) / 256, 256>>>(wv, wh + 2 * WN, nw4);
    conv_f16<<<(nw4 + 255) / 256, 256>>>(wo, wh + 3 * WN, nw4);

    dim3 ggrid(DMODEL / 128, TOKENS / 128);   // (8, 256)
    gemm_f16<<<ggrid, 256, SMEM_DYN>>>(xh, wh + 0 * WN, bq, q);
    gemm_f16<<<ggrid, 256, SMEM_DYN>>>(xh, wh + 1 * WN, bk, k);
    gemm_f16<<<ggrid, 256, SMEM_DYN>>>(xh, wh + 2 * WN, bv, v);

    attn_kernel<<<TOKENS, 256>>>(q, k, v, ch);

    gemm_f16<<<ggrid, 256, SMEM_DYN>>>(ch, wh + 3 * WN, bo, out);
}

// round 9
// speedup vs baseline: 2.3394x; 1.0245x over previous
#include <cuda_runtime.h>
#include <cuda_fp16.h>
#include <cstdint>
#include <cstddef>

// Problem constants
#define BATCH   8
#define SEQ     4096
#define DMODEL  1024
#define NHEAD   16
#define DHEAD   64
#define TOKENS  (BATCH * SEQ)            // 32768
#define GK      DMODEL                   // GEMM K = 1024

// ---------------------------------------------------------------------------
// Static scratch (no cudaMalloc allowed)
// ---------------------------------------------------------------------------
__device__ __half g_qh [(size_t)TOKENS * DMODEL];
__device__ __half g_kh [(size_t)TOKENS * DMODEL];
__device__ __half g_vh [(size_t)TOKENS * DMODEL];
__device__ __half g_xh [(size_t)TOKENS * DMODEL];
__device__ __half g_ch [(size_t)TOKENS * DMODEL];
__device__ __half g_wh [4][(size_t)DMODEL * DMODEL];   // wq|wk|wv|wo fp16

// ---------------------------------------------------------------------------
__device__ __forceinline__ uint32_t smem_u32(const void* p) {
    uint32_t a;
    asm("{ .reg .u64 t; cvta.to.shared.u64 t, %1; cvt.u32.u64 %0, t; }"
        : "=r"(a) : "l"(p));
    return a;
}

__device__ __forceinline__ void ldsm_x4(uint32_t (&r)[4], uint32_t addr) {
    asm volatile("ldmatrix.sync.aligned.m8n8.x4.shared.b16 {%0,%1,%2,%3}, [%4];"
                 : "=r"(r[0]), "=r"(r[1]), "=r"(r[2]), "=r"(r[3]) : "r"(addr));
}

__device__ __forceinline__ void mma_f16(float (&d)[4], const uint32_t (&a)[4],
                                        const uint32_t* b) {
    asm volatile(
        "mma.sync.aligned.m16n8k16.row.col.f32.f16.f16.f32 "
        "{%0,%1,%2,%3}, {%4,%5,%6,%7}, {%8,%9}, {%0,%1,%2,%3};"
        : "+f"(d[0]), "+f"(d[1]), "+f"(d[2]), "+f"(d[3])
        : "r"(a[0]), "r"(a[1]), "r"(a[2]), "r"(a[3]), "r"(b[0]), "r"(b[1]));
}

__device__ __forceinline__ void cp16(uint32_t dst, const void* src) {
    asm volatile("cp.async.cg.shared.global [%0], [%1], 16;"
                 :: "r"(dst), "l"(src));
}

// ---------------------------------------------------------------------------
// fp32 -> fp16 convert (round-to-nearest), vectorized
// ---------------------------------------------------------------------------
__global__ void conv_f16(const float* __restrict__ src,
                         __half* __restrict__ dst, int n4) {
    int i = blockIdx.x * blockDim.x + threadIdx.x;
    if (i >= n4) return;
    float4 v = reinterpret_cast<const float4*>(src)[i];
    __half h[4] = { __float2half_rn(v.x), __float2half_rn(v.y),
                    __float2half_rn(v.z), __float2half_rn(v.w) };
    reinterpret_cast<uint2*>(dst)[i] = *reinterpret_cast<uint2*>(h);
}

// ---------------------------------------------------------------------------
// HMMA GEMM core: C[M,1024] = Ah @ Wh^T + bias (fp16, fp32 accum).
// CTA tile 128x128. K-chunk 128 (two 64-col subtiles), 2-stage cp.async.
// 8 warps (4 M x 2 N), warp tile 32x64, mma.sync m16n8k16.
// Subtile layout: 128 rows x 128B, SW128 xor swizzle.
// ---------------------------------------------------------------------------
#define CHUNK2      128
#define NCHUNK2     (GK / CHUNK2)        // 8
#define SUB_BYTES   16384                // 128 x 128B
#define STAGE_BYTES (4 * SUB_BYTES)      // A0 A1 W0 W1 = 65536
#define NSTAGE      2
#define SMEM_DYN    (NSTAGE * STAGE_BYTES)  // 131072

template <typename OutT>
__device__ __forceinline__ void gemm_core(
    const __half* __restrict__ Ah, const __half* __restrict__ Wh,
    const float* __restrict__ bias, OutT* __restrict__ C,
    int colN0, size_t rowM0, char* smem)
{
    const uint32_t sb = smem_u32(smem);
    const int tid  = threadIdx.x;
    const int wid  = tid >> 5;
    const int lane = tid & 31;
    const int wm   = wid & 3;
    const int wn   = wid >> 2;

    const char* srcA = (const char*)(Ah + rowM0 * GK);
    const char* srcW = (const char*)(Wh + (size_t)colN0 * GK);

    const int a_row = wm * 32 + (lane & 15);
    const int a_ku  = lane >> 4;
    const int b_row = wn * 64 + (lane & 7) + ((lane >> 4) << 3);
    const int b_ku  = (lane >> 3) & 1;

    float acc[2][8][4];
#pragma unroll
    for (int mi = 0; mi < 2; mi++)
#pragma unroll
        for (int nf = 0; nf < 8; nf++)
#pragma unroll
            for (int j = 0; j < 4; j++) acc[mi][nf][j] = 0.f;

    // loader: 16 x 16B per thread per chunk (4 subtiles x 1024 units)
    auto load_chunk = [&](int c) {
        const uint32_t stage = sb + (c & 1) * STAGE_BYTES;
        const int k0b = c * CHUNK2 * 2;      // 512B per chunk along K
#pragma unroll
        for (int u2 = 0; u2 < 16; u2++) {
            const int g   = tid + u2 * 256;  // 0..4095
            const int t   = g >> 10;         // 0,1=A halves; 2,3=W halves
            const int w   = g & 1023;
            const int row = w >> 3;
            const int u   = w & 7;
            const uint32_t dst = stage + t * SUB_BYTES + row * 128
                               + ((u ^ (row & 7)) << 4);
            const char* src = (t < 2) ? srcA : srcW;
            const int half128 = (t & 1) * 128;
            cp16(dst, src + (size_t)row * 2048 + k0b + half128 + u * 16);
        }
        asm volatile("cp.async.commit_group;" ::: "memory");
    };

    load_chunk(0);

    for (int c = 0; c < NCHUNK2; c++) {
        if (c + 1 < NCHUNK2) {
            load_chunk(c + 1);
            asm volatile("cp.async.wait_group 1;" ::: "memory");
        } else {
            asm volatile("cp.async.wait_group 0;" ::: "memory");
        }
        __syncthreads();

        const uint32_t stage = sb + (c & 1) * STAGE_BYTES;

#pragma unroll
        for (int ks = 0; ks < 8; ks++) {
            const uint32_t t_ah = stage + (ks >> 2) * SUB_BYTES;
            const uint32_t t_wh = stage + 2 * SUB_BYTES + (ks >> 2) * SUB_BYTES;
            const int kl = ks & 3;
            uint32_t ah[2][4];
#pragma unroll
            for (int mi = 0; mi < 2; mi++) {
                const int row = a_row + mi * 16;
                const int u   = kl * 2 + a_ku;
                const uint32_t off = row * 128 + ((u ^ (row & 7)) << 4);
                ldsm_x4(ah[mi], t_ah + off);
            }
            uint32_t bh[4][4];
#pragma unroll
            for (int gg = 0; gg < 4; gg++) {
                const int row = b_row + gg * 16;
                const int u   = kl * 2 + b_ku;
                const uint32_t off = row * 128 + ((u ^ (row & 7)) << 4);
                ldsm_x4(bh[gg], t_wh + off);
            }
#pragma unroll
            for (int mi = 0; mi < 2; mi++)
#pragma unroll
                for (int gg = 0; gg < 4; gg++)
#pragma unroll
                    for (int sub = 0; sub < 2; sub++)
                        mma_f16(acc[mi][gg * 2 + sub], ah[mi], &bh[gg][sub * 2]);
        }
        __syncthreads();
    }

    // Epilogue
#pragma unroll
    for (int mi = 0; mi < 2; mi++) {
#pragma unroll
        for (int nf = 0; nf < 8; nf++) {
            const int col = colN0 + wn * 64 + nf * 8 + (lane & 3) * 2;
            const float2 bv2 = *reinterpret_cast<const float2*>(bias + col);
#pragma unroll
            for (int rh = 0; rh < 2; rh++) {
                const size_t row = rowM0 + wm * 32 + mi * 16 + (lane >> 2) + rh * 8;
                const float ox = acc[mi][nf][rh * 2 + 0] + bv2.x;
                const float oy = acc[mi][nf][rh * 2 + 1] + bv2.y;
                if constexpr (sizeof(OutT) == 2) {
                    *reinterpret_cast<__half2*>((__half*)C + row * DMODEL + col) =
                        __floats2half2_rn(ox, oy);
                } else {
                    float2 o; o.x = ox; o.y = oy;
                    *reinterpret_cast<float2*>((float*)C + row * DMODEL + col) = o;
                }
            }
        }
    }
}

// Fused QKV projection: grid (24, 256); blockIdx.x -> (weight sel, N tile)
__global__ __launch_bounds__(256, 1) void gemm_qkv(
    const __half* __restrict__ Ah, const __half* __restrict__ Wh,
    const float* __restrict__ bq, const float* __restrict__ bk,
    const float* __restrict__ bv,
    __half* __restrict__ Q, __half* __restrict__ K, __half* __restrict__ V)
{
    extern __shared__ __align__(1024) char smem[];
    const int wsel  = blockIdx.x >> 3;
    const int colN0 = (blockIdx.x & 7) * 128;
    const size_t rowM0 = (size_t)blockIdx.y * 128;
    const size_t WN = (size_t)DMODEL * DMODEL;

    const float* bias = (wsel == 0) ? bq : (wsel == 1) ? bk : bv;
    __half*      C    = (wsel == 0) ? Q  : (wsel == 1) ? K  : V;
    gemm_core<__half>(Ah, Wh + wsel * WN, bias, C, colN0, rowM0, smem);
}

// Output projection: fp32 out
__global__ __launch_bounds__(256, 1) void gemm_out(
    const __half* __restrict__ Ah, const __half* __restrict__ Wh,
    const float* __restrict__ bias, float* __restrict__ C)
{
    extern __shared__ __align__(1024) char smem[];
    gemm_core<float>(Ah, Wh, bias, C, blockIdx.x * 128,
                     (size_t)blockIdx.y * 128, smem);
}

// ---------------------------------------------------------------------------
// Per-token attention, fp16 q/k/v in smem (half the LDS/DRAM bytes of R7).
// scores fp32, softmax over head axis, fp16 ctx out.
// ---------------------------------------------------------------------------
__global__ __launch_bounds__(256) void attn_kernel(
    const __half* __restrict__ Q, const __half* __restrict__ K,
    const __half* __restrict__ V, __half* __restrict__ CH)
{
    const size_t base = (size_t)blockIdx.x * DMODEL;
    __shared__ __half sq[DMODEL];
    __shared__ __half sk[DMODEL];
    __shared__ __half sv[DMODEL];
    __shared__ float  sp[NHEAD][NHEAD];

    const int tid = threadIdx.x;
    // 1024 halves = 128 uint4 per array
    if (tid < 128) {
        reinterpret_cast<uint4*>(sq)[tid] = reinterpret_cast<const uint4*>(Q + base)[tid];
        reinterpret_cast<uint4*>(sk)[tid] = reinterpret_cast<const uint4*>(K + base)[tid];
    } else {
        reinterpret_cast<uint4*>(sv)[tid - 128] =
            reinterpret_cast<const uint4*>(V + base)[tid - 128];
    }
    __syncthreads();

    const int h = tid >> 4;
    const int g = tid & 15;
    const int rot = tid & 31;
    float s = 0.f;
#pragma unroll
    for (int dd = 0; dd < DHEAD; dd++) {
        const int d = (dd + rot) & (DHEAD - 1);
        s = fmaf(__half2float(sq[h * DHEAD + d]),
                 __half2float(sk[g * DHEAD + d]), s);
    }
    s *= 0.125f;

    float m = s;
#pragma unroll
    for (int o = 8; o > 0; o >>= 1) m = fmaxf(m, __shfl_xor_sync(0xFFFFFFFFu, m, o, 16));
    const float e = __expf(s - m);
    float sum = e;
#pragma unroll
    for (int o = 8; o > 0; o >>= 1) sum += __shfl_xor_sync(0xFFFFFFFFu, sum, o, 16);
    sp[h][g] = e / sum;
    __syncthreads();

#pragma unroll
    for (int r = 0; r < 4; r++) {
        const int idx = tid + r * 256;
        const int hh  = idx >> 6;
        const int d   = idx & (DHEAD - 1);
        float a = 0.f;
#pragma unroll
        for (int gg = 0; gg < NHEAD; gg++)
            a = fmaf(sp[hh][gg], __half2float(sv[gg * DHEAD + d]), a);
        CH[base + idx] = __float2half_rn(a);
    }
}

// ---------------------------------------------------------------------------
extern "C" void kernel_launch(void* const* d_in, const int* in_sizes, int n_in,
                              void* d_out, int out_size)
{
    const float* x  = (const float*)d_in[0];
    const float* wq = (const float*)d_in[1];
    const float* bq = (const float*)d_in[2];
    const float* wk = (const float*)d_in[3];
    const float* bk = (const float*)d_in[4];
    const float* wv = (const float*)d_in[5];
    const float* bv = (const float*)d_in[6];
    const float* wo = (const float*)d_in[7];
    const float* bo = (const float*)d_in[8];
    float* out = (float*)d_out;

    __half *qh, *kh, *vh, *xh, *ch, *wh;
    cudaGetSymbolAddress((void**)&qh, g_qh);
    cudaGetSymbolAddress((void**)&kh, g_kh);
    cudaGetSymbolAddress((void**)&vh, g_vh);
    cudaGetSymbolAddress((void**)&xh, g_xh);
    cudaGetSymbolAddress((void**)&ch, g_ch);
    cudaGetSymbolAddress((void**)&wh, g_wh);

    cudaFuncSetAttribute(gemm_qkv,
                         cudaFuncAttributeMaxDynamicSharedMemorySize, SMEM_DYN);
    cudaFuncSetAttribute(gemm_out,
                         cudaFuncAttributeMaxDynamicSharedMemorySize, SMEM_DYN);

    const size_t WN = (size_t)DMODEL * DMODEL;
    const int nx4 = (TOKENS * DMODEL) / 4;
    const int nw4 = (int)(WN / 4);

    conv_f16<<<(nx4 + 255) / 256, 256>>>(x, xh, nx4);
    conv_f16<<<(nw4 + 255) / 256, 256>>>(wq, wh + 0 * WN, nw4);
    conv_f16<<<(nw4 + 255) / 256, 256>>>(wk, wh + 1 * WN, nw4);
    conv_f16<<<(nw4 + 255) / 256, 256>>>(wv, wh + 2 * WN, nw4);
    conv_f16<<<(nw4 + 255) / 256, 256>>>(wo, wh + 3 * WN, nw4);

    dim3 qkvgrid(24, TOKENS / 128);       // 3 weights x 8 N-tiles, 256 M-tiles
    gemm_qkv<<<qkvgrid, 256, SMEM_DYN>>>(xh, wh, bq, bk, bv, qh, kh, vh);

    attn_kernel<<<TOKENS, 256>>>(qh, kh, vh, ch);

    dim3 ogrid(DMODEL / 128, TOKENS / 128);
    gemm_out<<<ogrid, 256, SMEM_DYN>>>(ch, wh + 3 * WN, bo, out);
}

// round 10
// speedup vs baseline: 2.4315x; 1.0394x over previous
#include <cuda_runtime.h>
#include <cuda_fp16.h>
#include <cstdint>
#include <cstddef>

// Problem constants
#define BATCH   8
#define SEQ     4096
#define DMODEL  1024
#define NHEAD   16
#define DHEAD   64
#define TOKENS  (BATCH * SEQ)            // 32768
#define GK      DMODEL                   // GEMM K = 1024

// ---------------------------------------------------------------------------
// Static scratch (no cudaMalloc allowed)
// ---------------------------------------------------------------------------
__device__ __half g_qh [(size_t)TOKENS * DMODEL];
__device__ __half g_kh [(size_t)TOKENS * DMODEL];
__device__ __half g_vh [(size_t)TOKENS * DMODEL];
__device__ __half g_xh [(size_t)TOKENS * DMODEL];
__device__ __half g_ch [(size_t)TOKENS * DMODEL];
__device__ __half g_wh [4][(size_t)DMODEL * DMODEL];   // wq|wk|wv|wo fp16

// ---------------------------------------------------------------------------
__device__ __forceinline__ uint32_t smem_u32(const void* p) {
    uint32_t a;
    asm("{ .reg .u64 t; cvta.to.shared.u64 t, %1; cvt.u32.u64 %0, t; }"
        : "=r"(a) : "l"(p));
    return a;
}

__device__ __forceinline__ void ldsm_x4(uint32_t (&r)[4], uint32_t addr) {
    asm volatile("ldmatrix.sync.aligned.m8n8.x4.shared.b16 {%0,%1,%2,%3}, [%4];"
                 : "=r"(r[0]), "=r"(r[1]), "=r"(r[2]), "=r"(r[3]) : "r"(addr));
}

__device__ __forceinline__ void mma_f16(float (&d)[4], const uint32_t (&a)[4],
                                        const uint32_t* b) {
    asm volatile(
        "mma.sync.aligned.m16n8k16.row.col.f32.f16.f16.f32 "
        "{%0,%1,%2,%3}, {%4,%5,%6,%7}, {%8,%9}, {%0,%1,%2,%3};"
        : "+f"(d[0]), "+f"(d[1]), "+f"(d[2]), "+f"(d[3])
        : "r"(a[0]), "r"(a[1]), "r"(a[2]), "r"(a[3]), "r"(b[0]), "r"(b[1]));
}

__device__ __forceinline__ void cp16(uint32_t dst, const void* src) {
    asm volatile("cp.async.cg.shared.global [%0], [%1], 16;"
                 :: "r"(dst), "l"(src));
}

// ---------------------------------------------------------------------------
// fp32 -> fp16 converts
// ---------------------------------------------------------------------------
__global__ void conv_f16(const float* __restrict__ src,
                         __half* __restrict__ dst, int n4) {
    int i = blockIdx.x * blockDim.x + threadIdx.x;
    if (i >= n4) return;
    float4 v = reinterpret_cast<const float4*>(src)[i];
    __half h[4] = { __float2half_rn(v.x), __float2half_rn(v.y),
                    __float2half_rn(v.z), __float2half_rn(v.w) };
    reinterpret_cast<uint2*>(dst)[i] = *reinterpret_cast<uint2*>(h);
}

// All four weight matrices in one launch: grid.y selects the weight.
__global__ void conv_w4(const float* __restrict__ w0, const float* __restrict__ w1,
                        const float* __restrict__ w2, const float* __restrict__ w3,
                        __half* __restrict__ dst, int n4) {
    int i = blockIdx.x * blockDim.x + threadIdx.x;
    if (i >= n4) return;
    const float* src = (blockIdx.y == 0) ? w0 : (blockIdx.y == 1) ? w1
                     : (blockIdx.y == 2) ? w2 : w3;
    float4 v = reinterpret_cast<const float4*>(src)[i];
    __half h[4] = { __float2half_rn(v.x), __float2half_rn(v.y),
                    __float2half_rn(v.z), __float2half_rn(v.w) };
    reinterpret_cast<uint2*>(dst + (size_t)blockIdx.y * DMODEL * DMODEL)[i] =
        *reinterpret_cast<uint2*>(h);
}

// ---------------------------------------------------------------------------
// HMMA GEMM core: C[M,1024] = Ah @ Wh^T + bias (fp16, fp32 accum).
// CTA tile 256x128. K-chunk 64, 3-stage cp.async pipeline.
// 8 warps (4 M x 2 N), warp tile 64x64, mma.sync m16n8k16.
// SMEM: A tile 256 rows x 128B (32KB), W tile 128 rows x 128B (16KB).
// SW128 xor swizzle -> conflict-free ldmatrix.
// ---------------------------------------------------------------------------
#define CHUNK       64
#define NCHUNK      (GK / CHUNK)          // 16
#define A_BYTES     32768                 // 256 x 128B
#define W_BYTES     16384                 // 128 x 128B
#define STAGE_BYTES (A_BYTES + W_BYTES)   // 49152
#define NSTAGE      3
#define SMEM_DYN    (NSTAGE * STAGE_BYTES)  // 147456

template <typename OutT>
__device__ __forceinline__ void gemm_core(
    const __half* __restrict__ Ah, const __half* __restrict__ Wh,
    const float* __restrict__ bias, OutT* __restrict__ C,
    int colN0, size_t rowM0, char* smem)
{
    const uint32_t sb = smem_u32(smem);
    const int tid  = threadIdx.x;
    const int wid  = tid >> 5;
    const int lane = tid & 31;
    const int wm   = wid & 3;          // warp row: 64 M each
    const int wn   = wid >> 2;         // warp col: 64 N each

    const char* srcA = (const char*)(Ah + rowM0 * GK);
    const char* srcW = (const char*)(Wh + (size_t)colN0 * GK);

    const int a_row = wm * 64 + (lane & 15);                      // + mi*16
    const int a_ku  = lane >> 4;
    const int b_row = wn * 64 + (lane & 7) + ((lane >> 4) << 3);  // + gg*16
    const int b_ku  = (lane >> 3) & 1;

    float acc[4][8][4];
#pragma unroll
    for (int mi = 0; mi < 4; mi++)
#pragma unroll
        for (int nf = 0; nf < 8; nf++)
#pragma unroll
            for (int j = 0; j < 4; j++) acc[mi][nf][j] = 0.f;

    // loader: 12 x 16B per thread per chunk (A: 2048 units, W: 1024 units)
    auto load_chunk = [&](int c) {
        const uint32_t stage = sb + (c % NSTAGE) * STAGE_BYTES;
        const int k0b = c * CHUNK * 2;       // 128B per chunk along K
#pragma unroll
        for (int u2 = 0; u2 < 12; u2++) {
            const int g = tid + u2 * 256;    // 0..3071
            if (g < 2048) {                  // A: 256 rows x 8 units
                const int row = g >> 3;
                const int u   = g & 7;
                const uint32_t dst = stage + row * 128 + ((u ^ (row & 7)) << 4);
                cp16(dst, srcA + (size_t)row * 2048 + k0b + u * 16);
            } else {                         // W: 128 rows x 8 units
                const int w   = g - 2048;
                const int row = w >> 3;
                const int u   = w & 7;
                const uint32_t dst = stage + A_BYTES + row * 128
                                   + ((u ^ (row & 7)) << 4);
                cp16(dst, srcW + (size_t)row * 2048 + k0b + u * 16);
            }
        }
        asm volatile("cp.async.commit_group;" ::: "memory");
    };

    load_chunk(0);
    load_chunk(1);

    for (int c = 0; c < NCHUNK; c++) {
        if (c + 2 < NCHUNK) {
            load_chunk(c + 2);
            asm volatile("cp.async.wait_group 2;" ::: "memory");
        } else if (c + 1 < NCHUNK) {
            asm volatile("cp.async.wait_group 1;" ::: "memory");
        } else {
            asm volatile("cp.async.wait_group 0;" ::: "memory");
        }
        __syncthreads();

        const uint32_t stage = sb + (c % NSTAGE) * STAGE_BYTES;
        const uint32_t t_ah = stage;
        const uint32_t t_wh = stage + A_BYTES;

#pragma unroll
        for (int ks = 0; ks < 4; ks++) {
            uint32_t ah[4][4];
#pragma unroll
            for (int mi = 0; mi < 4; mi++) {
                const int row = a_row + mi * 16;
                const int u   = ks * 2 + a_ku;
                const uint32_t off = row * 128 + ((u ^ (row & 7)) << 4);
                ldsm_x4(ah[mi], t_ah + off);
            }
            uint32_t bh[4][4];
#pragma unroll
            for (int gg = 0; gg < 4; gg++) {
                const int row = b_row + gg * 16;
                const int u   = ks * 2 + b_ku;
                const uint32_t off = row * 128 + ((u ^ (row & 7)) << 4);
                ldsm_x4(bh[gg], t_wh + off);
            }
#pragma unroll
            for (int mi = 0; mi < 4; mi++)
#pragma unroll
                for (int gg = 0; gg < 4; gg++)
#pragma unroll
                    for (int sub = 0; sub < 2; sub++)
                        mma_f16(acc[mi][gg * 2 + sub], ah[mi], &bh[gg][sub * 2]);
        }
        __syncthreads();
    }

    // Epilogue
#pragma unroll
    for (int mi = 0; mi < 4; mi++) {
#pragma unroll
        for (int nf = 0; nf < 8; nf++) {
            const int col = colN0 + wn * 64 + nf * 8 + (lane & 3) * 2;
            const float2 bv2 = *reinterpret_cast<const float2*>(bias + col);
#pragma unroll
            for (int rh = 0; rh < 2; rh++) {
                const size_t row = rowM0 + wm * 64 + mi * 16 + (lane >> 2) + rh * 8;
                const float ox = acc[mi][nf][rh * 2 + 0] + bv2.x;
                const float oy = acc[mi][nf][rh * 2 + 1] + bv2.y;
                if constexpr (sizeof(OutT) == 2) {
                    *reinterpret_cast<__half2*>((__half*)C + row * DMODEL + col) =
                        __floats2half2_rn(ox, oy);
                } else {
                    float2 o; o.x = ox; o.y = oy;
                    *reinterpret_cast<float2*>((float*)C + row * DMODEL + col) = o;
                }
            }
        }
    }
}

// Fused QKV projection: grid (24, 128); blockIdx.x -> (weight sel, N tile)
__global__ __launch_bounds__(256, 1) void gemm_qkv(
    const __half* __restrict__ Ah, const __half* __restrict__ Wh,
    const float* __restrict__ bq, const float* __restrict__ bk,
    const float* __restrict__ bv,
    __half* __restrict__ Q, __half* __restrict__ K, __half* __restrict__ V)
{
    extern __shared__ __align__(1024) char smem[];
    const int wsel  = blockIdx.x >> 3;
    const int colN0 = (blockIdx.x & 7) * 128;
    const size_t rowM0 = (size_t)blockIdx.y * 256;
    const size_t WN = (size_t)DMODEL * DMODEL;

    const float* bias = (wsel == 0) ? bq : (wsel == 1) ? bk : bv;
    __half*      C    = (wsel == 0) ? Q  : (wsel == 1) ? K  : V;
    gemm_core<__half>(Ah, Wh + wsel * WN, bias, C, colN0, rowM0, smem);
}

// Output projection: fp32 out
__global__ __launch_bounds__(256, 1) void gemm_out(
    const __half* __restrict__ Ah, const __half* __restrict__ Wh,
    const float* __restrict__ bias, float* __restrict__ C)
{
    extern __shared__ __align__(1024) char smem[];
    gemm_core<float>(Ah, Wh, bias, C, blockIdx.x * 128,
                     (size_t)blockIdx.y * 256, smem);
}

// ---------------------------------------------------------------------------
// Per-token attention, fp16 q/k/v in smem; scores fp32, fp16 ctx out.
// ---------------------------------------------------------------------------
__global__ __launch_bounds__(256) void attn_kernel(
    const __half* __restrict__ Q, const __half* __restrict__ K,
    const __half* __restrict__ V, __half* __restrict__ CH)
{
    const size_t base = (size_t)blockIdx.x * DMODEL;
    __shared__ __half sq[DMODEL];
    __shared__ __half sk[DMODEL];
    __shared__ __half sv[DMODEL];
    __shared__ float  sp[NHEAD][NHEAD];

    const int tid = threadIdx.x;
    if (tid < 128) {
        reinterpret_cast<uint4*>(sq)[tid] = reinterpret_cast<const uint4*>(Q + base)[tid];
        reinterpret_cast<uint4*>(sk)[tid] = reinterpret_cast<const uint4*>(K + base)[tid];
    } else {
        reinterpret_cast<uint4*>(sv)[tid - 128] =
            reinterpret_cast<const uint4*>(V + base)[tid - 128];
    }
    __syncthreads();

    const int h = tid >> 4;
    const int g = tid & 15;
    const int rot = tid & 31;
    float s = 0.f;
#pragma unroll
    for (int dd = 0; dd < DHEAD; dd++) {
        const int d = (dd + rot) & (DHEAD - 1);
        s = fmaf(__half2float(sq[h * DHEAD + d]),
                 __half2float(sk[g * DHEAD + d]), s);
    }
    s *= 0.125f;

    float m = s;
#pragma unroll
    for (int o = 8; o > 0; o >>= 1) m = fmaxf(m, __shfl_xor_sync(0xFFFFFFFFu, m, o, 16));
    const float e = __expf(s - m);
    float sum = e;
#pragma unroll
    for (int o = 8; o > 0; o >>= 1) sum += __shfl_xor_sync(0xFFFFFFFFu, sum, o, 16);
    sp[h][g] = e / sum;
    __syncthreads();

#pragma unroll
    for (int r = 0; r < 4; r++) {
        const int idx = tid + r * 256;
        const int hh  = idx >> 6;
        const int d   = idx & (DHEAD - 1);
        float a = 0.f;
#pragma unroll
        for (int gg = 0; gg < NHEAD; gg++)
            a = fmaf(sp[hh][gg], __half2float(sv[gg * DHEAD + d]), a);
        CH[base + idx] = __float2half_rn(a);
    }
}

// ---------------------------------------------------------------------------
extern "C" void kernel_launch(void* const* d_in, const int* in_sizes, int n_in,
                              void* d_out, int out_size)
{
    const float* x  = (const float*)d_in[0];
    const float* wq = (const float*)d_in[1];
    const float* bq = (const float*)d_in[2];
    const float* wk = (const float*)d_in[3];
    const float* bk = (const float*)d_in[4];
    const float* wv = (const float*)d_in[5];
    const float* bv = (const float*)d_in[6];
    const float* wo = (const float*)d_in[7];
    const float* bo = (const float*)d_in[8];
    float* out = (float*)d_out;

    __half *qh, *kh, *vh, *xh, *ch, *wh;
    cudaGetSymbolAddress((void**)&qh, g_qh);
    cudaGetSymbolAddress((void**)&kh, g_kh);
    cudaGetSymbolAddress((void**)&vh, g_vh);
    cudaGetSymbolAddress((void**)&xh, g_xh);
    cudaGetSymbolAddress((void**)&ch, g_ch);
    cudaGetSymbolAddress((void**)&wh, g_wh);

    cudaFuncSetAttribute(gemm_qkv,
                         cudaFuncAttributeMaxDynamicSharedMemorySize, SMEM_DYN);
    cudaFuncSetAttribute(gemm_out,
                         cudaFuncAttributeMaxDynamicSharedMemorySize, SMEM_DYN);

    const size_t WN = (size_t)DMODEL * DMODEL;
    const int nx4 = (TOKENS * DMODEL) / 4;
    const int nw4 = (int)(WN / 4);

    conv_f16<<<(nx4 + 255) / 256, 256>>>(x, xh, nx4);
    dim3 wgrid((nw4 + 255) / 256, 4);
    conv_w4<<<wgrid, 256>>>(wq, wk, wv, wo, wh, nw4);

    dim3 qkvgrid(24, TOKENS / 256);       // 3 weights x 8 N-tiles, 128 M-tiles
    gemm_qkv<<<qkvgrid, 256, SMEM_DYN>>>(xh, wh, bq, bk, bv, qh, kh, vh);

    attn_kernel<<<TOKENS, 256>>>(qh, kh, vh, ch);

    dim3 ogrid(DMODEL / 128, TOKENS / 256);
    gemm_out<<<ogrid, 256, SMEM_DYN>>>(ch, wh + 3 * WN, bo, out);
}

// round 12
// speedup vs baseline: 2.6863x; 1.1048x over previous
#include <cuda_runtime.h>
#include <cuda_fp16.h>
#include <cstdint>
#include <cstddef>

// Problem constants
#define BATCH   8
#define SEQ     4096
#define DMODEL  1024
#define NHEAD   16
#define DHEAD   64
#define TOKENS  (BATCH * SEQ)            // 32768
#define GK      DMODEL                   // GEMM K = 1024

// ---------------------------------------------------------------------------
// Static scratch (no cudaMalloc allowed)
// ---------------------------------------------------------------------------
__device__ __half g_qh [(size_t)TOKENS * DMODEL];
__device__ __half g_kh [(size_t)TOKENS * DMODEL];
__device__ __half g_vh [(size_t)TOKENS * DMODEL];
__device__ __half g_xh [(size_t)TOKENS * DMODEL];
__device__ __half g_ch [(size_t)TOKENS * DMODEL];
__device__ __half g_wh [4][(size_t)DMODEL * DMODEL];   // wq|wk|wv|wo fp16

// ---------------------------------------------------------------------------
__device__ __forceinline__ uint32_t smem_u32(const void* p) {
    uint32_t a;
    asm("{ .reg .u64 t; cvta.to.shared.u64 t, %1; cvt.u32.u64 %0, t; }"
        : "=r"(a) : "l"(p));
    return a;
}

__device__ __forceinline__ void ldsm_x4(uint32_t (&r)[4], uint32_t addr) {
    asm volatile("ldmatrix.sync.aligned.m8n8.x4.shared.b16 {%0,%1,%2,%3}, [%4];"
                 : "=r"(r[0]), "=r"(r[1]), "=r"(r[2]), "=r"(r[3]) : "r"(addr));
}

__device__ __forceinline__ void mma_f16(float (&d)[4], const uint32_t (&a)[4],
                                        const uint32_t* b) {
    asm volatile(
        "mma.sync.aligned.m16n8k16.row.col.f32.f16.f16.f32 "
        "{%0,%1,%2,%3}, {%4,%5,%6,%7}, {%8,%9}, {%0,%1,%2,%3};"
        : "+f"(d[0]), "+f"(d[1]), "+f"(d[2]), "+f"(d[3])
        : "r"(a[0]), "r"(a[1]), "r"(a[2]), "r"(a[3]), "r"(b[0]), "r"(b[1]));
}

__device__ __forceinline__ void cp16(uint32_t dst, const void* src) {
    asm volatile("cp.async.cg.shared.global [%0], [%1], 16;"
                 :: "r"(dst), "l"(src));
}

// ---------------------------------------------------------------------------
// fp32 -> fp16 converts
// ---------------------------------------------------------------------------
__global__ void conv_f16(const float* __restrict__ src,
                         __half* __restrict__ dst, int n4) {
    int i = blockIdx.x * blockDim.x + threadIdx.x;
    if (i >= n4) return;
    float4 v = reinterpret_cast<const float4*>(src)[i];
    __half h[4] = { __float2half_rn(v.x), __float2half_rn(v.y),
                    __float2half_rn(v.z), __float2half_rn(v.w) };
    reinterpret_cast<uint2*>(dst)[i] = *reinterpret_cast<uint2*>(h);
}

__global__ void conv_w4(const float* __restrict__ w0, const float* __restrict__ w1,
                        const float* __restrict__ w2, const float* __restrict__ w3,
                        __half* __restrict__ dst, int n4) {
    int i = blockIdx.x * blockDim.x + threadIdx.x;
    if (i >= n4) return;
    const float* src = (blockIdx.y == 0) ? w0 : (blockIdx.y == 1) ? w1
                     : (blockIdx.y == 2) ? w2 : w3;
    float4 v = reinterpret_cast<const float4*>(src)[i];
    __half h[4] = { __float2half_rn(v.x), __float2half_rn(v.y),
                    __float2half_rn(v.z), __float2half_rn(v.w) };
    reinterpret_cast<uint2*>(dst + (size_t)blockIdx.y * DMODEL * DMODEL)[i] =
        *reinterpret_cast<uint2*>(h);
}

// ---------------------------------------------------------------------------
// HMMA GEMM core (unchanged from R10): CTA 256x128, K-chunk 64, 3-stage.
// 8 warps (4 M x 2 N), warp tile 64x64, mma.sync m16n8k16.
// ---------------------------------------------------------------------------
#define CHUNK       64
#define NCHUNK      (GK / CHUNK)          // 16
#define A_BYTES     32768                 // 256 x 128B
#define W_BYTES     16384                 // 128 x 128B
#define STAGE_BYTES (A_BYTES + W_BYTES)   // 49152
#define NSTAGE      3
#define SMEM_DYN    (NSTAGE * STAGE_BYTES)  // 147456

template <typename OutT>
__device__ __forceinline__ void gemm_core(
    const __half* __restrict__ Ah, const __half* __restrict__ Wh,
    const float* __restrict__ bias, OutT* __restrict__ C,
    int colN0, size_t rowM0, char* smem)
{
    const uint32_t sb = smem_u32(smem);
    const int tid  = threadIdx.x;
    const int wid  = tid >> 5;
    const int lane = tid & 31;
    const int wm   = wid & 3;
    const int wn   = wid >> 2;

    const char* srcA = (const char*)(Ah + rowM0 * GK);
    const char* srcW = (const char*)(Wh + (size_t)colN0 * GK);

    const int a_row = wm * 64 + (lane & 15);
    const int a_ku  = lane >> 4;
    const int b_row = wn * 64 + (lane & 7) + ((lane >> 4) << 3);
    const int b_ku  = (lane >> 3) & 1;

    float acc[4][8][4];
#pragma unroll
    for (int mi = 0; mi < 4; mi++)
#pragma unroll
        for (int nf = 0; nf < 8; nf++)
#pragma unroll
            for (int j = 0; j < 4; j++) acc[mi][nf][j] = 0.f;

    auto load_chunk = [&](int c) {
        const uint32_t stage = sb + (c % NSTAGE) * STAGE_BYTES;
        const int k0b = c * CHUNK * 2;
#pragma unroll
        for (int u2 = 0; u2 < 12; u2++) {
            const int g = tid + u2 * 256;
            if (g < 2048) {
                const int row = g >> 3;
                const int u   = g & 7;
                const uint32_t dst = stage + row * 128 + ((u ^ (row & 7)) << 4);
                cp16(dst, srcA + (size_t)row * 2048 + k0b + u * 16);
            } else {
                const int w   = g - 2048;
                const int row = w >> 3;
                const int u   = w & 7;
                const uint32_t dst = stage + A_BYTES + row * 128
                                   + ((u ^ (row & 7)) << 4);
                cp16(dst, srcW + (size_t)row * 2048 + k0b + u * 16);
            }
        }
        asm volatile("cp.async.commit_group;" ::: "memory");
    };

    load_chunk(0);
    load_chunk(1);

    for (int c = 0; c < NCHUNK; c++) {
        if (c + 2 < NCHUNK) {
            load_chunk(c + 2);
            asm volatile("cp.async.wait_group 2;" ::: "memory");
        } else if (c + 1 < NCHUNK) {
            asm volatile("cp.async.wait_group 1;" ::: "memory");
        } else {
            asm volatile("cp.async.wait_group 0;" ::: "memory");
        }
        __syncthreads();

        const uint32_t stage = sb + (c % NSTAGE) * STAGE_BYTES;
        const uint32_t t_ah = stage;
        const uint32_t t_wh = stage + A_BYTES;

#pragma unroll
        for (int ks = 0; ks < 4; ks++) {
            uint32_t ah[4][4];
#pragma unroll
            for (int mi = 0; mi < 4; mi++) {
                const int row = a_row + mi * 16;
                const int u   = ks * 2 + a_ku;
                const uint32_t off = row * 128 + ((u ^ (row & 7)) << 4);
                ldsm_x4(ah[mi], t_ah + off);
            }
            uint32_t bh[4][4];
#pragma unroll
            for (int gg = 0; gg < 4; gg++) {
                const int row = b_row + gg * 16;
                const int u   = ks * 2 + b_ku;
                const uint32_t off = row * 128 + ((u ^ (row & 7)) << 4);
                ldsm_x4(bh[gg], t_wh + off);
            }
#pragma unroll
            for (int mi = 0; mi < 4; mi++)
#pragma unroll
                for (int gg = 0; gg < 4; gg++)
#pragma unroll
                    for (int sub = 0; sub < 2; sub++)
                        mma_f16(acc[mi][gg * 2 + sub], ah[mi], &bh[gg][sub * 2]);
        }
        __syncthreads();
    }

#pragma unroll
    for (int mi = 0; mi < 4; mi++) {
#pragma unroll
        for (int nf = 0; nf < 8; nf++) {
            const int col = colN0 + wn * 64 + nf * 8 + (lane & 3) * 2;
            const float2 bv2 = *reinterpret_cast<const float2*>(bias + col);
#pragma unroll
            for (int rh = 0; rh < 2; rh++) {
                const size_t row = rowM0 + wm * 64 + mi * 16 + (lane >> 2) + rh * 8;
                const float ox = acc[mi][nf][rh * 2 + 0] + bv2.x;
                const float oy = acc[mi][nf][rh * 2 + 1] + bv2.y;
                if constexpr (sizeof(OutT) == 2) {
                    *reinterpret_cast<__half2*>((__half*)C + row * DMODEL + col) =
                        __floats2half2_rn(ox, oy);
                } else {
                    float2 o; o.x = ox; o.y = oy;
                    *reinterpret_cast<float2*>((float*)C + row * DMODEL + col) = o;
                }
            }
        }
    }
}

__global__ __launch_bounds__(256, 1) void gemm_qkv(
    const __half* __restrict__ Ah, const __half* __restrict__ Wh,
    const float* __restrict__ bq, const float* __restrict__ bk,
    const float* __restrict__ bv,
    __half* __restrict__ Q, __half* __restrict__ K, __half* __restrict__ V)
{
    extern __shared__ __align__(1024) char smem[];
    const int wsel  = blockIdx.x >> 3;
    const int colN0 = (blockIdx.x & 7) * 128;
    const size_t rowM0 = (size_t)blockIdx.y * 256;
    const size_t WN = (size_t)DMODEL * DMODEL;

    const float* bias = (wsel == 0) ? bq : (wsel == 1) ? bk : bv;
    __half*      C    = (wsel == 0) ? Q  : (wsel == 1) ? K  : V;
    gemm_core<__half>(Ah, Wh + wsel * WN, bias, C, colN0, rowM0, smem);
}

__global__ __launch_bounds__(256, 1) void gemm_out(
    const __half* __restrict__ Ah, const __half* __restrict__ Wh,
    const float* __restrict__ bias, float* __restrict__ C)
{
    extern __shared__ __align__(1024) char smem[];
    gemm_core<float>(Ah, Wh, bias, C, blockIdx.x * 128,
                     (size_t)blockIdx.y * 256, smem);
}

// ---------------------------------------------------------------------------
// Per-token attention — vectorized shared accesses.
// Scores: half2 loads (LDS.32, rotated, bank-conflict-free).
// Probs:  sp row read as float4 (LDS.128 broadcast).
// Ctx:    half2 v loads + half2 stores; fp32 accumulation throughout.
// ---------------------------------------------------------------------------
__global__ __launch_bounds__(256) void attn_kernel(
    const __half* __restrict__ Q, const __half* __restrict__ K,
    const __half* __restrict__ V, __half* __restrict__ CH)
{
    const size_t base = (size_t)blockIdx.x * DMODEL;
    __shared__ __half sq[DMODEL];
    __shared__ __half sk[DMODEL];
    __shared__ __half sv[DMODEL];
    __shared__ float  sp[NHEAD][NHEAD];

    const int tid = threadIdx.x;
    if (tid < 128) {
        reinterpret_cast<uint4*>(sq)[tid] = reinterpret_cast<const uint4*>(Q + base)[tid];
        reinterpret_cast<uint4*>(sk)[tid] = reinterpret_cast<const uint4*>(K + base)[tid];
    } else {
        reinterpret_cast<uint4*>(sv)[tid - 128] =
            reinterpret_cast<const uint4*>(V + base)[tid - 128];
    }
    __syncthreads();

    const __half2* sq2 = reinterpret_cast<const __half2*>(sq);
    const __half2* sk2 = reinterpret_cast<const __half2*>(sk);
    const __half2* sv2 = reinterpret_cast<const __half2*>(sv);

    // ---- scores: one (h,g) per thread; 32 half2 pairs along d ----
    const int h    = tid >> 4;
    const int g    = tid & 15;
    const int lane = tid & 31;
    float s = 0.f;
#pragma unroll
    for (int jj = 0; jj < 32; jj++) {
        const int j = (jj + lane) & 31;   // rotated: all 32 banks distinct
        const float2 a = __half22float2(sq2[h * 32 + j]);
        const float2 b = __half22float2(sk2[g * 32 + j]);
        s = fmaf(a.x, b.x, s);
        s = fmaf(a.y, b.y, s);
    }
    s *= 0.125f;   // 1/sqrt(64)

    // ---- softmax over g (16-lane shuffle groups) ----
    float m = s;
#pragma unroll
    for (int o = 8; o > 0; o >>= 1) m = fmaxf(m, __shfl_xor_sync(0xFFFFFFFFu, m, o, 16));
    const float e = __expf(s - m);
    float sum = e;
#pragma unroll
    for (int o = 8; o > 0; o >>= 1) sum += __shfl_xor_sync(0xFFFFFFFFu, sum, o, 16);
    sp[h][g] = e / sum;
    __syncthreads();

    // ---- ctx: 2 half2 outputs per thread (512 half2 total) ----
    __half2* out2 = reinterpret_cast<__half2*>(CH + base);
#pragma unroll
    for (int r = 0; r < 2; r++) {
        const int idx2 = tid + r * 256;   // 0..511
        const int hh   = idx2 >> 5;       // head
        const int d2   = idx2 & 31;       // half2 index within head
        // probability row as 4 x float4 (broadcast within 32-thread groups)
        float pr[16];
        *reinterpret_cast<float4*>(&pr[0])  = *reinterpret_cast<const float4*>(&sp[hh][0]);
        *reinterpret_cast<float4*>(&pr[4])  = *reinterpret_cast<const float4*>(&sp[hh][4]);
        *reinterpret_cast<float4*>(&pr[8])  = *reinterpret_cast<const float4*>(&sp[hh][8]);
        *reinterpret_cast<float4*>(&pr[12]) = *reinterpret_cast<const float4*>(&sp[hh][12]);
        float ax = 0.f, ay = 0.f;
#pragma unroll
        for (int gg = 0; gg < 16; gg++) {
            const float2 v = __half22float2(sv2[gg * 32 + d2]);
            ax = fmaf(pr[gg], v.x, ax);
            ay = fmaf(pr[gg], v.y, ay);
        }
        out2[hh * 32 + d2] = __floats2half2_rn(ax, ay);
    }
}

// ---------------------------------------------------------------------------
extern "C" void kernel_launch(void* const* d_in, const int* in_sizes, int n_in,
                              void* d_out, int out_size)
{
    const float* x  = (const float*)d_in[0];
    const float* wq = (const float*)d_in[1];
    const float* bq = (const float*)d_in[2];
    const float* wk = (const float*)d_in[3];
    const float* bk = (const float*)d_in[4];
    const float* wv = (const float*)d_in[5];
    const float* bv = (const float*)d_in[6];
    const float* wo = (const float*)d_in[7];
    const float* bo = (const float*)d_in[8];
    float* out = (float*)d_out;

    __half *qh, *kh, *vh, *xh, *ch, *wh;
    cudaGetSymbolAddress((void**)&qh, g_qh);
    cudaGetSymbolAddress((void**)&kh, g_kh);
    cudaGetSymbolAddress((void**)&vh, g_vh);
    cudaGetSymbolAddress((void**)&xh, g_xh);
    cudaGetSymbolAddress((void**)&ch, g_ch);
    cudaGetSymbolAddress((void**)&wh, g_wh);

    cudaFuncSetAttribute(gemm_qkv,
                         cudaFuncAttributeMaxDynamicSharedMemorySize, SMEM_DYN);
    cudaFuncSetAttribute(gemm_out,
                         cudaFuncAttributeMaxDynamicSharedMemorySize, SMEM_DYN);

    const size_t WN = (size_t)DMODEL * DMODEL;
    const int nx4 = (TOKENS * DMODEL) / 4;
    const int nw4 = (int)(WN / 4);

    conv_f16<<<(nx4 + 255) / 256, 256>>>(x, xh, nx4);
    dim3 wgrid((nw4 + 255) / 256, 4);
    conv_w4<<<wgrid, 256>>>(wq, wk, wv, wo, wh, nw4);

    dim3 qkvgrid(24, TOKENS / 256);
    gemm_qkv<<<qkvgrid, 256, SMEM_DYN>>>(xh, wh, bq, bk, bv, qh, kh, vh);

    attn_kernel<<<TOKENS, 256>>>(qh, kh, vh, ch);

    dim3 ogrid(DMODEL / 128, TOKENS / 256);
    gemm_out<<<ogrid, 256, SMEM_DYN>>>(ch, wh + 3 * WN, bo, out);
}